// round 1
// baseline (speedup 1.0000x reference)
#include <cuda_runtime.h>

// Problem constants (fixed by the dataset)
#define NMAX 100000
#define EMAX 3200000
#define F 64
#define GMAX 64

// Scratch (device globals — no allocation allowed)
__device__ __align__(16) float g_nw[EMAX];            // normalized edge weights
__device__ float g_deg[NMAX];                          // unweighted in-degree
__device__ float g_degw[NMAX];                         // weighted in-degree
__device__ __align__(16) float g_acc[NMAX * F];        // neighbor accumulator
__device__ __align__(16) float g_h1[NMAX * F];         // layer-1 activations
__device__ __align__(16) float g_h2[NMAX * F];         // layer-2 activations
__device__ __align__(16) float g_pool[GMAX * F];       // per-graph sums
__device__ float g_cnt[GMAX];                          // per-graph node counts

// ---------------------------------------------------------------------------
// Zero all accumulators (start of pipeline)
// ---------------------------------------------------------------------------
__global__ void k_zero(int n, int g) {
    int stride = gridDim.x * blockDim.x;
    int total = n * F;
    for (int i = blockIdx.x * blockDim.x + threadIdx.x; i < total; i += stride) {
        g_acc[i] = 0.f;
        if (i < n) { g_deg[i] = 0.f; g_degw[i] = 0.f; }
        if (i < g * F) g_pool[i] = 0.f;
        if (i < g) g_cnt[i] = 0.f;
    }
}

// ---------------------------------------------------------------------------
// Per-edge degree accumulation: weighted + unweighted in-degree at dst
// ---------------------------------------------------------------------------
__global__ void k_deg(const float* __restrict__ ew, const int* __restrict__ dst, int e) {
    int i = blockIdx.x * blockDim.x + threadIdx.x;
    if (i < e) {
        int d = dst[i];
        atomicAdd(&g_degw[d], ew[i]);
        atomicAdd(&g_deg[d], 1.0f);
    }
}

// ---------------------------------------------------------------------------
// Edge scatter: acc[dst] += h[src] * nw.  Half-warp (16 lanes) per edge,
// float4 per lane, vectorized red.global.add.v4.f32 (sm_90+).
// FIRST: compute nw = ew / degw[dst] on the fly and persist for layer 2.
// ---------------------------------------------------------------------------
template <bool FIRST>
__global__ void k_scatter(const float* __restrict__ h,
                          const float* __restrict__ ew,
                          const int* __restrict__ src,
                          const int* __restrict__ dst,
                          int e) {
    int t = blockIdx.x * blockDim.x + threadIdx.x;
    int grp = t >> 4;          // edge index
    int sub = t & 15;          // float4 slot within the 64-float row
    if (grp >= e) return;

    int s = src[grp];
    int d = dst[grp];
    float w;
    if (FIRST) {
        w = ew[grp] / g_degw[d];
        if (sub == 0) g_nw[grp] = w;
    } else {
        w = g_nw[grp];
    }

    float4 v = reinterpret_cast<const float4*>(h)[s * 16 + sub];
    v.x *= w; v.y *= w; v.z *= w; v.w *= w;

    float4* p = reinterpret_cast<float4*>(g_acc) + d * 16 + sub;
    asm volatile("red.global.add.v4.f32 [%0], {%1,%2,%3,%4};"
                 :: "l"(p), "f"(v.x), "f"(v.y), "f"(v.z), "f"(v.w)
                 : "memory");
}

// ---------------------------------------------------------------------------
// Node transform: h_out = relu( ((acc + h_in)/(deg+1)) @ W + b )
// One warp per node; W (64x64) in SMEM; lane computes output cols lane, lane+32.
// Optionally re-zeroes acc in place (fused zeroing for the next layer).
// ---------------------------------------------------------------------------
__global__ void __launch_bounds__(128)
k_transform(const float* __restrict__ h_in,
            const float* __restrict__ W,
            const float* __restrict__ b,
            float* __restrict__ h_out,
            int n, int zero_acc) {
    __shared__ float Ws[F * F];
    __shared__ float bs[F];
    __shared__ float xs[4][F];

    for (int i = threadIdx.x; i < F * F; i += 128) Ws[i] = W[i];
    if (threadIdx.x < F) bs[threadIdx.x] = b[threadIdx.x];
    __syncthreads();

    int warp = threadIdx.x >> 5;
    int lane = threadIdx.x & 31;

    for (int node = blockIdx.x * 4 + warp; node < n; node += gridDim.x * 4) {
        float inv = 1.0f / (g_deg[node] + 1.0f);
        int base = node * F;

        float x0 = (g_acc[base + lane]      + h_in[base + lane])      * inv;
        float x1 = (g_acc[base + lane + 32] + h_in[base + lane + 32]) * inv;
        if (zero_acc) {
            g_acc[base + lane] = 0.f;
            g_acc[base + lane + 32] = 0.f;
        }
        xs[warp][lane] = x0;
        xs[warp][lane + 32] = x1;
        __syncwarp();

        float a0 = bs[lane];
        float a1 = bs[lane + 32];
        #pragma unroll
        for (int k = 0; k < F; k++) {
            float xk = xs[warp][k];
            a0 = fmaf(xk, Ws[k * F + lane],      a0);
            a1 = fmaf(xk, Ws[k * F + lane + 32], a1);
        }
        h_out[base + lane]      = fmaxf(a0, 0.f);
        h_out[base + lane + 32] = fmaxf(a1, 0.f);
        __syncwarp();
    }
}

// ---------------------------------------------------------------------------
// Graph pooling: graph_ids is sorted, so each warp walks a contiguous node
// range, accumulates runs in registers, and flushes one atomic group per
// graph transition.
// ---------------------------------------------------------------------------
__global__ void k_pool(const float* __restrict__ h, const int* __restrict__ gid, int n) {
    int wid = (blockIdx.x * blockDim.x + threadIdx.x) >> 5;
    int lane = threadIdx.x & 31;
    int nwarps = (gridDim.x * blockDim.x) >> 5;
    int chunk = (n + nwarps - 1) / nwarps;
    int start = wid * chunk;
    int end = min(start + chunk, n);
    if (start >= end) return;

    int cur = -1;
    float s0 = 0.f, s1 = 0.f, c = 0.f;
    for (int node = start; node < end; node++) {
        int g = gid[node];
        if (g != cur) {
            if (cur >= 0) {
                atomicAdd(&g_pool[cur * F + lane], s0);
                atomicAdd(&g_pool[cur * F + lane + 32], s1);
                if (lane == 0) atomicAdd(&g_cnt[cur], c);
            }
            cur = g; s0 = s1 = 0.f; c = 0.f;
        }
        s0 += h[node * F + lane];
        s1 += h[node * F + lane + 32];
        c += 1.f;
    }
    if (cur >= 0) {
        atomicAdd(&g_pool[cur * F + lane], s0);
        atomicAdd(&g_pool[cur * F + lane + 32], s1);
        if (lane == 0) atomicAdd(&g_cnt[cur], c);
    }
}

// ---------------------------------------------------------------------------
// Final classifier: out[g,c] = (pool[g]/cnt[g]) @ Wc + bc.  One tiny block.
// ---------------------------------------------------------------------------
__global__ void k_final(const float* __restrict__ Wc, const float* __restrict__ bc,
                        float* __restrict__ out, int g) {
    int t = threadIdx.x;
    if (t >= g * 2) return;
    int gi = t >> 1;
    int c = t & 1;
    float inv = 1.0f / fmaxf(g_cnt[gi], 1.0f);
    float s = bc[c];
    #pragma unroll
    for (int f = 0; f < F; f++)
        s = fmaf(g_pool[gi * F + f] * inv, Wc[f * 2 + c], s);
    out[t] = s;
}

// ---------------------------------------------------------------------------
// Launch
// ---------------------------------------------------------------------------
extern "C" void kernel_launch(void* const* d_in, const int* in_sizes, int n_in,
                              void* d_out, int out_size) {
    const float* in_feat = (const float*)d_in[0];
    const float* ew      = (const float*)d_in[1];
    const float* W1      = (const float*)d_in[2];
    const float* b1      = (const float*)d_in[3];
    const float* W2      = (const float*)d_in[4];
    const float* b2      = (const float*)d_in[5];
    const float* Wc      = (const float*)d_in[6];
    const float* bc      = (const float*)d_in[7];
    const int*   src     = (const int*)d_in[8];
    const int*   dst     = (const int*)d_in[9];
    const int*   gid     = (const int*)d_in[10];

    int n = in_sizes[0] / F;
    int e = in_sizes[1];
    int g = out_size / 2;

    void* p_h1 = nullptr;
    void* p_h2 = nullptr;
    cudaGetSymbolAddress(&p_h1, g_h1);
    cudaGetSymbolAddress(&p_h2, g_h2);
    float* h1 = (float*)p_h1;
    float* h2 = (float*)p_h2;

    // 1. zero accumulators
    k_zero<<<4096, 256>>>(n, g);
    // 2. degrees
    k_deg<<<(e + 255) / 256, 256>>>(ew, dst, e);
    // 3. layer 1: scatter (computes & persists nw) + transform (re-zeroes acc)
    int sthreads_blocks = (e * 16 + 255) / 256;
    k_scatter<true><<<sthreads_blocks, 256>>>(in_feat, ew, src, dst, e);
    k_transform<<<148 * 8, 128>>>(in_feat, W1, b1, h1, n, /*zero_acc=*/1);
    // 4. layer 2
    k_scatter<false><<<sthreads_blocks, 256>>>(h1, ew, src, dst, e);
    k_transform<<<148 * 8, 128>>>(h1, W2, b2, h2, n, /*zero_acc=*/0);
    // 5. pooling + classifier
    k_pool<<<512, 256>>>(h2, gid, n);
    k_final<<<1, 128>>>(Wc, bc, (float*)d_out, g);
}

// round 3
// speedup vs baseline: 1.2802x; 1.2802x over previous
#include <cuda_runtime.h>

#define NMAX 100000
#define EMAX 3200000
#define F 64
#define GMAX 64

struct __align__(8) EdgeT { int s; float w; };

// Scratch (device globals — no allocation allowed)
__device__ int   g_deg_i[NMAX];          // unweighted in-degree (int)
__device__ float g_degw[NMAX];           // weighted in-degree
__device__ int   g_off[NMAX + 1];        // CSR offsets
__device__ int   g_tmp[NMAX];            // running fill cursors
__device__ EdgeT g_csr[EMAX];            // CSR records {src, nw}
__device__ __align__(16) float g_x[NMAX * F];    // (acc+h)/(deg+1) — GEMM input
__device__ __align__(16) float g_h1[NMAX * F];   // layer-1 activations
__device__ __align__(16) float g_h2[NMAX * F];   // layer-2 activations
__device__ __align__(16) float g_pool[GMAX * F];
__device__ float g_cnt[GMAX];

// ---------------------------------------------------------------------------
__global__ void k_zero(int n, int g) {
    int stride = gridDim.x * blockDim.x;
    for (int i = blockIdx.x * blockDim.x + threadIdx.x; i < n; i += stride) {
        g_deg_i[i] = 0;
        g_degw[i] = 0.f;
        if (i < g * F) g_pool[i] = 0.f;
        if (i < g) g_cnt[i] = 0.f;
    }
}

// ---------------------------------------------------------------------------
// Per-edge degree accumulation: weighted degree (float) + count (int)
// ---------------------------------------------------------------------------
__global__ void k_deg(const float* __restrict__ ew, const int* __restrict__ dst, int e) {
    int i = blockIdx.x * blockDim.x + threadIdx.x;
    if (i < e) {
        int d = dst[i];
        atomicAdd(&g_degw[d], ew[i]);
        atomicAdd(&g_deg_i[d], 1);
    }
}

// ---------------------------------------------------------------------------
// Single-block exclusive scan of g_deg_i -> g_off, g_tmp
// ---------------------------------------------------------------------------
__global__ void __launch_bounds__(1024) k_scan(int n) {
    __shared__ int partial[1024];
    int t = threadIdx.x;
    int chunk = (n + 1023) >> 10;
    int lo = t * chunk;
    int hi = min(lo + chunk, n);

    int s = 0;
    for (int i = lo; i < hi; i++) s += g_deg_i[i];
    partial[t] = s;
    __syncthreads();

    // inclusive Hillis-Steele scan
    for (int d = 1; d < 1024; d <<= 1) {
        int v = (t >= d) ? partial[t - d] : 0;
        __syncthreads();
        partial[t] += v;
        __syncthreads();
    }

    int run = (t == 0) ? 0 : partial[t - 1];
    for (int i = lo; i < hi; i++) {
        g_off[i] = run;
        g_tmp[i] = run;
        run += g_deg_i[i];
    }
    if (t == 0) g_off[n] = partial[1023];
}

// ---------------------------------------------------------------------------
// CSR fill: place {src, normalized weight} record per edge, grouped by dst
// ---------------------------------------------------------------------------
__global__ void k_fill(const float* __restrict__ ew, const int* __restrict__ src,
                       const int* __restrict__ dst, int e) {
    int i = blockIdx.x * blockDim.x + threadIdx.x;
    if (i < e) {
        int d = dst[i];
        int pos = atomicAdd(&g_tmp[d], 1);
        EdgeT rec;
        rec.s = src[i];
        rec.w = ew[i] / g_degw[d];
        g_csr[pos] = rec;
    }
}

// ---------------------------------------------------------------------------
// Gather: warp per dst node. x[node] = (sum_e nw*h[src_e] + h[node])/(deg+1)
// Edge loop unrolled x4 to batch independent loads (MLP).
// ---------------------------------------------------------------------------
__global__ void __launch_bounds__(256) k_gather(const float* __restrict__ h, int n) {
    int w = (blockIdx.x * blockDim.x + threadIdx.x) >> 5;
    int l = threadIdx.x & 31;
    if (w >= n) return;

    int beg = g_off[w];
    int end = g_off[w + 1];
    float a0 = 0.f, a1 = 0.f;

    int e = beg;
    for (; e + 4 <= end; e += 4) {
        EdgeT e0 = g_csr[e + 0];
        EdgeT e1 = g_csr[e + 1];
        EdgeT e2 = g_csr[e + 2];
        EdgeT e3 = g_csr[e + 3];
        float v00 = h[e0.s * F + l], v01 = h[e0.s * F + 32 + l];
        float v10 = h[e1.s * F + l], v11 = h[e1.s * F + 32 + l];
        float v20 = h[e2.s * F + l], v21 = h[e2.s * F + 32 + l];
        float v30 = h[e3.s * F + l], v31 = h[e3.s * F + 32 + l];
        a0 = fmaf(e0.w, v00, a0); a1 = fmaf(e0.w, v01, a1);
        a0 = fmaf(e1.w, v10, a0); a1 = fmaf(e1.w, v11, a1);
        a0 = fmaf(e2.w, v20, a0); a1 = fmaf(e2.w, v21, a1);
        a0 = fmaf(e3.w, v30, a0); a1 = fmaf(e3.w, v31, a1);
    }
    for (; e < end; e++) {
        EdgeT ed = g_csr[e];
        a0 = fmaf(ed.w, h[ed.s * F + l], a0);
        a1 = fmaf(ed.w, h[ed.s * F + 32 + l], a1);
    }

    float inv = 1.0f / (float(end - beg) + 1.0f);
    g_x[w * F + l]      = (a0 + h[w * F + l]) * inv;
    g_x[w * F + 32 + l] = (a1 + h[w * F + 32 + l]) * inv;
}

// ---------------------------------------------------------------------------
// Register-tiled GEMM: out = relu(x @ W + b). Tile 64 nodes x 64 cols,
// 128 threads, 4 nodes x 8 cols per thread. x transposed through padded smem.
// ---------------------------------------------------------------------------
__global__ void __launch_bounds__(128) k_gemm(const float* __restrict__ x,
                                              const float* __restrict__ W,
                                              const float* __restrict__ b,
                                              float* __restrict__ out, int n) {
    __shared__ float xsT[F][F + 1];   // [k][node], pitch 65
    __shared__ float Ws[F][F];        // [k][col]
    __shared__ float bs[F];

    int t = threadIdx.x;
    for (int i = t; i < F * F; i += 128) Ws[i >> 6][i & 63] = W[i];
    if (t < F) bs[t] = b[t];

    int base = blockIdx.x * 64;

    // load + transpose x tile (zero-fill past n)
    #pragma unroll
    for (int j = 0; j < 8; j++) {
        int f = t + 128 * j;     // float4 index within tile, 0..1023
        int nl = f >> 4;         // local node 0..63
        int k4 = f & 15;         // float4 slot within row
        int gn = base + nl;
        float4 v = make_float4(0.f, 0.f, 0.f, 0.f);
        if (gn < n) v = reinterpret_cast<const float4*>(x)[gn * 16 + k4];
        xsT[k4 * 4 + 0][nl] = v.x;
        xsT[k4 * 4 + 1][nl] = v.y;
        xsT[k4 * 4 + 2][nl] = v.z;
        xsT[k4 * 4 + 3][nl] = v.w;
    }
    __syncthreads();

    int ng = t & 15;    // node group: local nodes ng*4 .. ng*4+3
    int cg = t >> 4;    // col group:  cols cg*8 .. cg*8+7

    float acc[4][8];
    #pragma unroll
    for (int i = 0; i < 4; i++)
        #pragma unroll
        for (int j = 0; j < 8; j++) acc[i][j] = bs[cg * 8 + j];

    #pragma unroll 8
    for (int k = 0; k < F; k++) {
        float xf[4];
        #pragma unroll
        for (int i = 0; i < 4; i++) xf[i] = xsT[k][ng * 4 + i];
        float4 wa = *reinterpret_cast<float4*>(&Ws[k][cg * 8]);
        float4 wb = *reinterpret_cast<float4*>(&Ws[k][cg * 8 + 4]);
        #pragma unroll
        for (int i = 0; i < 4; i++) {
            acc[i][0] = fmaf(xf[i], wa.x, acc[i][0]);
            acc[i][1] = fmaf(xf[i], wa.y, acc[i][1]);
            acc[i][2] = fmaf(xf[i], wa.z, acc[i][2]);
            acc[i][3] = fmaf(xf[i], wa.w, acc[i][3]);
            acc[i][4] = fmaf(xf[i], wb.x, acc[i][4]);
            acc[i][5] = fmaf(xf[i], wb.y, acc[i][5]);
            acc[i][6] = fmaf(xf[i], wb.z, acc[i][6]);
            acc[i][7] = fmaf(xf[i], wb.w, acc[i][7]);
        }
    }

    #pragma unroll
    for (int i = 0; i < 4; i++) {
        int gn = base + ng * 4 + i;
        if (gn < n) {
            float4 o0, o1;
            o0.x = fmaxf(acc[i][0], 0.f); o0.y = fmaxf(acc[i][1], 0.f);
            o0.z = fmaxf(acc[i][2], 0.f); o0.w = fmaxf(acc[i][3], 0.f);
            o1.x = fmaxf(acc[i][4], 0.f); o1.y = fmaxf(acc[i][5], 0.f);
            o1.z = fmaxf(acc[i][6], 0.f); o1.w = fmaxf(acc[i][7], 0.f);
            reinterpret_cast<float4*>(out)[gn * 16 + cg * 2]     = o0;
            reinterpret_cast<float4*>(out)[gn * 16 + cg * 2 + 1] = o1;
        }
    }
}

// ---------------------------------------------------------------------------
// Graph pooling: graph_ids sorted -> register run accumulation per warp
// ---------------------------------------------------------------------------
__global__ void k_pool(const float* __restrict__ h, const int* __restrict__ gid, int n) {
    int wid = (blockIdx.x * blockDim.x + threadIdx.x) >> 5;
    int lane = threadIdx.x & 31;
    int nwarps = (gridDim.x * blockDim.x) >> 5;
    int chunk = (n + nwarps - 1) / nwarps;
    int start = wid * chunk;
    int end = min(start + chunk, n);
    if (start >= end) return;

    int cur = -1;
    float s0 = 0.f, s1 = 0.f, c = 0.f;
    for (int node = start; node < end; node++) {
        int g = gid[node];
        if (g != cur) {
            if (cur >= 0) {
                atomicAdd(&g_pool[cur * F + lane], s0);
                atomicAdd(&g_pool[cur * F + lane + 32], s1);
                if (lane == 0) atomicAdd(&g_cnt[cur], c);
            }
            cur = g; s0 = s1 = 0.f; c = 0.f;
        }
        s0 += h[node * F + lane];
        s1 += h[node * F + lane + 32];
        c += 1.f;
    }
    if (cur >= 0) {
        atomicAdd(&g_pool[cur * F + lane], s0);
        atomicAdd(&g_pool[cur * F + lane + 32], s1);
        if (lane == 0) atomicAdd(&g_cnt[cur], c);
    }
}

// ---------------------------------------------------------------------------
__global__ void k_final(const float* __restrict__ Wc, const float* __restrict__ bc,
                        float* __restrict__ out, int g) {
    int t = threadIdx.x;
    if (t >= g * 2) return;
    int gi = t >> 1;
    int c = t & 1;
    float inv = 1.0f / fmaxf(g_cnt[gi], 1.0f);
    float s = bc[c];
    #pragma unroll
    for (int f = 0; f < F; f++)
        s = fmaf(g_pool[gi * F + f] * inv, Wc[f * 2 + c], s);
    out[t] = s;
}

// ---------------------------------------------------------------------------
extern "C" void kernel_launch(void* const* d_in, const int* in_sizes, int n_in,
                              void* d_out, int out_size) {
    const float* in_feat = (const float*)d_in[0];
    const float* ew      = (const float*)d_in[1];
    const float* W1      = (const float*)d_in[2];
    const float* b1      = (const float*)d_in[3];
    const float* W2      = (const float*)d_in[4];
    const float* b2      = (const float*)d_in[5];
    const float* Wc      = (const float*)d_in[6];
    const float* bc      = (const float*)d_in[7];
    const int*   src     = (const int*)d_in[8];
    const int*   dst     = (const int*)d_in[9];
    const int*   gid     = (const int*)d_in[10];

    int n = in_sizes[0] / F;
    int e = in_sizes[1];
    int g = out_size / 2;

    void *p_x = nullptr, *p_h1 = nullptr, *p_h2 = nullptr;
    cudaGetSymbolAddress(&p_x, g_x);
    cudaGetSymbolAddress(&p_h1, g_h1);
    cudaGetSymbolAddress(&p_h2, g_h2);
    float* xbuf = (float*)p_x;
    float* h1 = (float*)p_h1;
    float* h2 = (float*)p_h2;

    int eb = (e + 255) / 256;
    int nwb = (n * 32 + 255) / 256;     // warp-per-node
    int tiles = (n + 63) / 64;

    // CSR build
    k_zero<<<512, 256>>>(n, g);
    k_deg<<<eb, 256>>>(ew, dst, e);
    k_scan<<<1, 1024>>>(n);
    k_fill<<<eb, 256>>>(ew, src, dst, e);

    // layer 1
    k_gather<<<nwb, 256>>>(in_feat, n);
    k_gemm<<<tiles, 128>>>(xbuf, W1, b1, h1, n);
    // layer 2
    k_gather<<<nwb, 256>>>(h1, n);
    k_gemm<<<tiles, 128>>>(xbuf, W2, b2, h2, n);

    // pooling + classifier
    k_pool<<<512, 256>>>(h2, gid, n);
    k_final<<<1, 128>>>(Wc, bc, (float*)d_out, g);
}